// round 4
// baseline (speedup 1.0000x reference)
#include <cuda_runtime.h>

#define HH 256
#define WW 256
#define NI 16
#define CC 3
#define HW (HH * WW)

struct Tap { int i00, i10, i01, i11; float w00, w10, w01, w11; };

// coef folded into the weights
__device__ __forceinline__ Tap make_tap(float ix, float iy, float coef) {
    Tap t;
    const int x0 = __float2int_rd(ix);
    const int y0 = __float2int_rd(iy);
    const float wx1 = ix - (float)x0;
    const float wy1 = iy - (float)y0;
    const float wx0 = 1.0f - wx1;
    const float wy0 = 1.0f - wy1;
    const int x1 = x0 + 1, y1 = y0 + 1;
    const bool vx0 = (x0 >= 0) & (x0 < WW);
    const bool vx1 = (x1 >= 0) & (x1 < WW);
    const bool vy0 = (y0 >= 0) & (y0 < HH);
    const bool vy1 = (y1 >= 0) & (y1 < HH);
    const int x0c = min(max(x0, 0), WW - 1);
    const int x1c = min(max(x1, 0), WW - 1);
    const int y0c = min(max(y0, 0), HH - 1);
    const int y1c = min(max(y1, 0), HH - 1);
    const float wy0c = wy0 * coef;
    const float wy1c = wy1 * coef;
    t.w00 = wx0 * wy0c * ((vx0 & vy0) ? 1.0f : 0.0f);
    t.w10 = wx1 * wy0c * ((vx1 & vy0) ? 1.0f : 0.0f);
    t.w01 = wx0 * wy1c * ((vx0 & vy1) ? 1.0f : 0.0f);
    t.w11 = wx1 * wy1c * ((vx1 & vy1) ? 1.0f : 0.0f);
    t.i00 = y0c * WW + x0c;
    t.i10 = y0c * WW + x1c;
    t.i01 = y1c * WW + x0c;
    t.i11 = y1c * WW + x1c;
    return t;
}

__device__ __forceinline__ float gather(const float* __restrict__ p, const Tap& t) {
    return t.w00 * __ldg(p + t.i00) + t.w10 * __ldg(p + t.i10)
         + t.w01 * __ldg(p + t.i01) + t.w11 * __ldg(p + t.i11);
}

__global__ __launch_bounds__(128, 12)
void warp_renderer_kernel(
    const float* __restrict__ g0,           // [B,NI,C,H,W]
    const float* __restrict__ m0,           // [B,NI,1,H,W]
    const float* __restrict__ mode_logits,  // [B,NI,5]
    const float* __restrict__ tp,           // [B,NI,6]
    const float* __restrict__ alpha,        // [B,NI,1]
    const float* __restrict__ inst_valid,   // [B,NI]
    const float* __restrict__ i_bg,         // [B,C,H,W]
    float* __restrict__ out,
    int B)
{
    __shared__ int   s_nact, s_ninact;
    __shared__ int   s_act_ni[NI];
    __shared__ float s_act_coef[NI];
    __shared__ float s_act_t0[NI], s_act_t3[NI];
    __shared__ float s_act_bx[NI], s_act_by[NI];
    __shared__ int   s_inact_ni[NI];

    const int b = blockIdx.x >> 8;        // blockIdx.x = b*H + y
    const int y = blockIdx.x & 255;

    // --- per-instance precompute + active compaction (lanes 0..15 of warp 0) ---
    if (threadIdx.x < NI) {
        const int lane = threadIdx.x;
        const int inst = b * NI + lane;
        const float* L = mode_logits + inst * 5;
        int mode = 0;
        float best = L[0];
        #pragma unroll
        for (int k = 1; k < 5; ++k) {
            float v = L[k];
            if (v > best) { best = v; mode = k; }  // first-max argmax
        }
        float coef;
        if (mode == 0 || mode == 2 || mode == 4) coef = 1.0f;       // static-like
        else if (mode == 3)                      coef = alpha[inst]; // blink
        else                                     coef = 0.0f;        // mode 1
        coef *= inst_valid[inst];

        const bool active = (coef != 0.0f);
        const unsigned mask = __ballot_sync(0x0000FFFFu, active);
        const unsigned lower = (1u << lane) - 1u;

        if (active) {
            const int pos = __popc(mask & lower);
            const float t0 = tp[inst * 6 + 0];
            const float t1 = tp[inst * 6 + 1];
            const float t2 = tp[inst * 6 + 2];
            const float t3 = tp[inst * 6 + 3];
            const float t4 = tp[inst * 6 + 4];
            const float t5 = tp[inst * 6 + 5];
            const float ys = (2.0f * (float)y + 1.0f) * (1.0f / (float)HH) - 1.0f;
            // ix = t0*x + bx ; iy = t3*x + by   (full chain folded)
            const float bx = 128.0f * (t1 * ys + t2) + 127.5f + 0.5f * t0 - 128.0f * t0;
            const float by = 128.0f * (t4 * ys + t5) + 127.5f + 0.5f * t3 - 128.0f * t3;
            s_act_ni[pos]   = lane;
            s_act_coef[pos] = coef;
            s_act_t0[pos]   = t0;
            s_act_t3[pos]   = t3;
            s_act_bx[pos]   = bx;
            s_act_by[pos]   = by;
        } else {
            const int pos = __popc((~mask) & 0xFFFFu & lower);
            s_inact_ni[pos] = lane;
        }
        if (lane == 0) {
            s_nact   = __popc(mask);
            s_ninact = NI - __popc(mask);
        }
    }
    __syncthreads();

    const int x0px = threadIdx.x * 2;           // first of the two pixels
    const int pix = y * WW + x0px;              // float2-aligned
    const float xf0 = (float)x0px;

    // output section offsets (all < 2^31 elements)
    const int n_gpi = B * NI * CC * HW;
    const int n_mpi = B * NI * HW;
    float* __restrict__ out_gpi  = out;
    float* __restrict__ out_mpi  = out + n_gpi;
    float* __restrict__ out_gmid = out + n_gpi + n_mpi;
    float* __restrict__ out_mmid = out_gmid + B * CC * HW;
    float* __restrict__ out_ibas = out_mmid + B * HW;

    // --- zero stores for inactive instances (float2) ---
    const float2 z2 = make_float2(0.0f, 0.0f);
    const int ninact = s_ninact;
    for (int k = 0; k < ninact; ++k) {
        const int ni = s_inact_ni[k];
        const int bgi = (b * NI + ni) * CC * HW + pix;
        const int bmi = (b * NI + ni) * HW + pix;
        *(float2*)(out_gpi + bgi)          = z2;
        *(float2*)(out_gpi + bgi + HW)     = z2;
        *(float2*)(out_gpi + bgi + 2 * HW) = z2;
        *(float2*)(out_mpi + bmi)          = z2;
    }

    float ga0 = 0.0f, ga1 = 0.0f;   // channel 0, px0/px1
    float gb0 = 0.0f, gb1 = 0.0f;   // channel 1
    float gc0 = 0.0f, gc1 = 0.0f;   // channel 2
    float ma0 = 0.0f, ma1 = 0.0f;   // mask

    // --- hot loop: active instances only, no branches ---
    const int nact = s_nact;
    for (int j = 0; j < nact; ++j) {
        const int   ni   = s_act_ni[j];
        const float coef = s_act_coef[j];
        const float t0   = s_act_t0[j];
        const float t3   = s_act_t3[j];
        const int base_g = (b * NI + ni) * CC * HW;
        const int base_m = (b * NI + ni) * HW;

        const float ix0 = fmaf(t0, xf0, s_act_bx[j]);
        const float iy0 = fmaf(t3, xf0, s_act_by[j]);
        const float ix1 = ix0 + t0;
        const float iy1 = iy0 + t3;

        const Tap ta = make_tap(ix0, iy0, coef);
        const Tap tb = make_tap(ix1, iy1, coef);

        const float* __restrict__ s0 = g0 + base_g;
        const float* __restrict__ s1 = s0 + HW;
        const float* __restrict__ s2 = s1 + HW;
        const float* __restrict__ sm = m0 + base_m;

        const float A0 = gather(s0, ta), A1 = gather(s0, tb);
        const float B0 = gather(s1, ta), B1 = gather(s1, tb);
        const float C0 = gather(s2, ta), C1 = gather(s2, tb);
        const float M0 = gather(sm, ta), M1 = gather(sm, tb);

        const float2 gv0 = make_float2(A0, A1);
        const float2 gv1 = make_float2(B0, B1);
        const float2 gv2 = make_float2(C0, C1);
        const float2 mv  = make_float2(M0, M1);

        *(float2*)(out_gpi + base_g + pix)          = gv0;
        *(float2*)(out_gpi + base_g + HW + pix)     = gv1;
        *(float2*)(out_gpi + base_g + 2 * HW + pix) = gv2;
        *(float2*)(out_mpi + base_m + pix)          = mv;

        ga0 += A0; ga1 += A1;
        gb0 += B0; gb1 += B1;
        gc0 += C0; gc1 += C1;
        ma0 += M0; ma1 += M1;
    }

    // --- reductions + composite (float2) ---
    const int bg = b * CC * HW + pix;
    *(float2*)(out_gmid + bg)          = make_float2(ga0, ga1);
    *(float2*)(out_gmid + bg + HW)     = make_float2(gb0, gb1);
    *(float2*)(out_gmid + bg + 2 * HW) = make_float2(gc0, gc1);
    *(float2*)(out_mmid + b * HW + pix) =
        make_float2(fminf(fmaxf(ma0, 0.0f), 1.0f), fminf(fmaxf(ma1, 0.0f), 1.0f));

    const float2 bg0 = *(const float2*)(i_bg + bg);
    const float2 bg1 = *(const float2*)(i_bg + bg + HW);
    const float2 bg2 = *(const float2*)(i_bg + bg + 2 * HW);
    *(float2*)(out_ibas + bg)          = make_float2(bg0.x + ga0, bg0.y + ga1);
    *(float2*)(out_ibas + bg + HW)     = make_float2(bg1.x + gb0, bg1.y + gb1);
    *(float2*)(out_ibas + bg + 2 * HW) = make_float2(bg2.x + gc0, bg2.y + gc1);
}

extern "C" void kernel_launch(void* const* d_in, const int* in_sizes, int n_in,
                              void* d_out, int out_size) {
    const float* g0          = (const float*)d_in[0];
    const float* m0          = (const float*)d_in[1];
    const float* mode_logits = (const float*)d_in[2];
    const float* tp          = (const float*)d_in[3];
    const float* alpha       = (const float*)d_in[4];
    const float* inst_valid  = (const float*)d_in[5];
    const float* i_bg        = (const float*)d_in[6];
    float* out = (float*)d_out;

    const int B = in_sizes[0] / (NI * CC * HW);

    dim3 grid(B * HH);
    dim3 block(WW / 2);   // 128 threads, 2 px each
    warp_renderer_kernel<<<grid, block>>>(g0, m0, mode_logits, tp, alpha,
                                          inst_valid, i_bg, out, B);
}

// round 5
// speedup vs baseline: 1.0062x; 1.0062x over previous
#include <cuda_runtime.h>

#define HH 256
#define WW 256
#define NI 16
#define CC 3
#define HW (HH * WW)

// ───────────────────────── Kernel A: per-(pixel, instance) warp ─────────────────────────
// grid = (B*H, NI), block = 256 (one row of one instance per block)
__global__ __launch_bounds__(256)
void warp_instance_kernel(
    const float* __restrict__ g0,           // [B,NI,C,H,W]
    const float* __restrict__ m0,           // [B,NI,1,H,W]
    const float* __restrict__ mode_logits,  // [B,NI,5]
    const float* __restrict__ tp,           // [B,NI,6]
    const float* __restrict__ alpha,        // [B,NI,1]
    const float* __restrict__ inst_valid,   // [B,NI]
    float* __restrict__ out_gpi,            // [B,NI,C,H,W]
    float* __restrict__ out_mpi)            // [B,NI,1,H,W]
{
    __shared__ float s_coef, s_t0, s_t3, s_bx, s_by;

    const int b  = blockIdx.x >> 8;
    const int y  = blockIdx.x & 255;
    const int ni = blockIdx.y;
    const int inst = b * NI + ni;

    if (threadIdx.x == 0) {
        const float* L = mode_logits + inst * 5;
        int mode = 0;
        float best = L[0];
        #pragma unroll
        for (int k = 1; k < 5; ++k) {
            float v = L[k];
            if (v > best) { best = v; mode = k; }  // first-max argmax
        }
        float coef;
        if (mode == 0 || mode == 2 || mode == 4) coef = 1.0f;       // static-like
        else if (mode == 3)                      coef = alpha[inst]; // blink
        else                                     coef = 0.0f;        // mode 1
        coef *= inst_valid[inst];
        s_coef = coef;

        const float t0 = tp[inst * 6 + 0];
        const float t1 = tp[inst * 6 + 1];
        const float t2 = tp[inst * 6 + 2];
        const float t3 = tp[inst * 6 + 3];
        const float t4 = tp[inst * 6 + 4];
        const float t5 = tp[inst * 6 + 5];
        const float ys = (2.0f * (float)y + 1.0f) * (1.0f / (float)HH) - 1.0f;
        // ix = t0*x + bx ; iy = t3*x + by   (full normalize/unnormalize chain folded)
        s_t0 = t0;
        s_t3 = t3;
        s_bx = 128.0f * (t1 * ys + t2) + 127.5f + 0.5f * t0 - 128.0f * t0;
        s_by = 128.0f * (t4 * ys + t5) + 127.5f + 0.5f * t3 - 128.0f * t3;
    }
    __syncthreads();

    const int x   = threadIdx.x;
    const int pix = y * WW + x;
    const int base_g = inst * CC * HW;
    const int base_m = inst * HW;
    const float coef = s_coef;

    if (coef == 0.0f) {   // block-uniform branch
        out_gpi[base_g + pix]          = 0.0f;
        out_gpi[base_g + HW + pix]     = 0.0f;
        out_gpi[base_g + 2 * HW + pix] = 0.0f;
        out_mpi[base_m + pix]          = 0.0f;
        return;
    }

    const float ix = fmaf(s_t0, (float)x, s_bx);
    const float iy = fmaf(s_t3, (float)x, s_by);

    const int x0 = __float2int_rd(ix);
    const int y0 = __float2int_rd(iy);
    const float wx1 = ix - (float)x0;
    const float wy1 = iy - (float)y0;
    const float wx0 = 1.0f - wx1;
    const float wy0 = 1.0f - wy1;
    const int x1 = x0 + 1, y1 = y0 + 1;

    const bool vx0 = (x0 >= 0) & (x0 < WW);
    const bool vx1 = (x1 >= 0) & (x1 < WW);
    const bool vy0 = (y0 >= 0) & (y0 < HH);
    const bool vy1 = (y1 >= 0) & (y1 < HH);

    const int x0c = min(max(x0, 0), WW - 1);
    const int x1c = min(max(x1, 0), WW - 1);
    const int y0c = min(max(y0, 0), HH - 1);
    const int y1c = min(max(y1, 0), HH - 1);

    const float wy0c = wy0 * coef;
    const float wy1c = wy1 * coef;
    const float w00 = wx0 * wy0c * ((vx0 & vy0) ? 1.0f : 0.0f);
    const float w10 = wx1 * wy0c * ((vx1 & vy0) ? 1.0f : 0.0f);
    const float w01 = wx0 * wy1c * ((vx0 & vy1) ? 1.0f : 0.0f);
    const float w11 = wx1 * wy1c * ((vx1 & vy1) ? 1.0f : 0.0f);

    const int i00 = y0c * WW + x0c;
    const int i10 = y0c * WW + x1c;
    const int i01 = y1c * WW + x0c;
    const int i11 = y1c * WW + x1c;

    const float* __restrict__ s0 = g0 + base_g;
    const float* __restrict__ s1 = s0 + HW;
    const float* __restrict__ s2 = s1 + HW;
    const float* __restrict__ sm = m0 + base_m;

    // 16 independent loads in flight
    const float a00 = __ldg(s0 + i00), a10 = __ldg(s0 + i10),
                a01 = __ldg(s0 + i01), a11 = __ldg(s0 + i11);
    const float b00 = __ldg(s1 + i00), b10 = __ldg(s1 + i10),
                b01 = __ldg(s1 + i01), b11 = __ldg(s1 + i11);
    const float c00 = __ldg(s2 + i00), c10 = __ldg(s2 + i10),
                c01 = __ldg(s2 + i01), c11 = __ldg(s2 + i11);
    const float d00 = __ldg(sm + i00), d10 = __ldg(sm + i10),
                d01 = __ldg(sm + i01), d11 = __ldg(sm + i11);

    out_gpi[base_g + pix]          = w00 * a00 + w10 * a10 + w01 * a01 + w11 * a11;
    out_gpi[base_g + HW + pix]     = w00 * b00 + w10 * b10 + w01 * b01 + w11 * b11;
    out_gpi[base_g + 2 * HW + pix] = w00 * c00 + w10 * c10 + w01 * c01 + w11 * c11;
    out_mpi[base_m + pix]          = w00 * d00 + w10 * d10 + w01 * d01 + w11 * d11;
}

// ───────────────────────── Kernel B: reduction + composite ─────────────────────────
// grid = B*H, block = 128 (2 px per thread, float2)
__global__ __launch_bounds__(128)
void reduce_kernel(
    const float* __restrict__ out_gpi,   // [B,NI,C,H,W]
    const float* __restrict__ out_mpi,   // [B,NI,1,H,W]
    const float* __restrict__ i_bg,      // [B,C,H,W]
    float* __restrict__ out_gmid,        // [B,C,H,W]
    float* __restrict__ out_mmid,        // [B,1,H,W]
    float* __restrict__ out_ibas)        // [B,C,H,W]
{
    const int b = blockIdx.x >> 8;
    const int y = blockIdx.x & 255;
    const int pix = y * WW + threadIdx.x * 2;

    float2 ga = make_float2(0.f, 0.f);
    float2 gb = make_float2(0.f, 0.f);
    float2 gc = make_float2(0.f, 0.f);
    float2 ma = make_float2(0.f, 0.f);

    #pragma unroll
    for (int ni = 0; ni < NI; ++ni) {
        const int base_g = (b * NI + ni) * CC * HW + pix;
        const int base_m = (b * NI + ni) * HW + pix;
        const float2 v0 = *(const float2*)(out_gpi + base_g);
        const float2 v1 = *(const float2*)(out_gpi + base_g + HW);
        const float2 v2 = *(const float2*)(out_gpi + base_g + 2 * HW);
        const float2 vm = *(const float2*)(out_mpi + base_m);
        ga.x += v0.x; ga.y += v0.y;
        gb.x += v1.x; gb.y += v1.y;
        gc.x += v2.x; gc.y += v2.y;
        ma.x += vm.x; ma.y += vm.y;
    }

    const int bg = b * CC * HW + pix;
    *(float2*)(out_gmid + bg)          = ga;
    *(float2*)(out_gmid + bg + HW)     = gb;
    *(float2*)(out_gmid + bg + 2 * HW) = gc;
    *(float2*)(out_mmid + b * HW + pix) =
        make_float2(fminf(fmaxf(ma.x, 0.0f), 1.0f), fminf(fmaxf(ma.y, 0.0f), 1.0f));

    const float2 bg0 = *(const float2*)(i_bg + bg);
    const float2 bg1 = *(const float2*)(i_bg + bg + HW);
    const float2 bg2 = *(const float2*)(i_bg + bg + 2 * HW);
    *(float2*)(out_ibas + bg)          = make_float2(bg0.x + ga.x, bg0.y + ga.y);
    *(float2*)(out_ibas + bg + HW)     = make_float2(bg1.x + gb.x, bg1.y + gb.y);
    *(float2*)(out_ibas + bg + 2 * HW) = make_float2(bg2.x + gc.x, bg2.y + gc.y);
}

extern "C" void kernel_launch(void* const* d_in, const int* in_sizes, int n_in,
                              void* d_out, int out_size) {
    const float* g0          = (const float*)d_in[0];
    const float* m0          = (const float*)d_in[1];
    const float* mode_logits = (const float*)d_in[2];
    const float* tp          = (const float*)d_in[3];
    const float* alpha       = (const float*)d_in[4];
    const float* inst_valid  = (const float*)d_in[5];
    const float* i_bg        = (const float*)d_in[6];
    float* out = (float*)d_out;

    const int B = in_sizes[0] / (NI * CC * HW);

    float* out_gpi  = out;
    float* out_mpi  = out + B * NI * CC * HW;
    float* out_gmid = out_mpi + B * NI * HW;
    float* out_mmid = out_gmid + B * CC * HW;
    float* out_ibas = out_mmid + B * HW;

    dim3 gridA(B * HH, NI);
    warp_instance_kernel<<<gridA, 256>>>(g0, m0, mode_logits, tp, alpha,
                                         inst_valid, out_gpi, out_mpi);

    dim3 gridB(B * HH);
    reduce_kernel<<<gridB, 128>>>(out_gpi, out_mpi, i_bg,
                                  out_gmid, out_mmid, out_ibas);
}

// round 6
// speedup vs baseline: 1.4152x; 1.4065x over previous
#include <cuda_runtime.h>

#define HH 256
#define WW 256
#define NI 16
#define CC 3
#define HW (HH * WW)

__device__ __forceinline__ void stcs(float* p, float v) {
#if __CUDA_ARCH__ >= 800
    __stcs(p, v);
#else
    *p = v;
#endif
}

__global__ __launch_bounds__(256, 7)
void warp_renderer_kernel(
    const float* __restrict__ g0,           // [B,NI,C,H,W]
    const float* __restrict__ m0,           // [B,NI,1,H,W]
    const float* __restrict__ mode_logits,  // [B,NI,5]
    const float* __restrict__ tp,           // [B,NI,6]
    const float* __restrict__ alpha,        // [B,NI,1]
    const float* __restrict__ inst_valid,   // [B,NI]
    const float* __restrict__ i_bg,         // [B,C,H,W]
    float* __restrict__ out,
    int B)
{
    __shared__ int   s_nact, s_ninact;
    __shared__ int   s_act_ni[NI];
    __shared__ float s_act_t0[NI], s_act_t3[NI];
    __shared__ float s_act_bx[NI], s_act_by[NI];
    __shared__ float s_act_coef[NI];
    __shared__ int   s_inact_ni[NI];

    const int b = blockIdx.x >> 8;        // blockIdx.x = b*H + y
    const int y = blockIdx.x & 255;
    const int x = threadIdx.x;

    // --- per-instance precompute + active compaction (lanes 0..15 of warp 0) ---
    if (threadIdx.x < NI) {
        const int lane = threadIdx.x;
        const int inst = b * NI + lane;
        const float* L = mode_logits + inst * 5;
        int mode = 0;
        float best = L[0];
        #pragma unroll
        for (int k = 1; k < 5; ++k) {
            float v = L[k];
            if (v > best) { best = v; mode = k; }  // first-max argmax
        }
        float coef;
        if (mode == 0 || mode == 2 || mode == 4) coef = 1.0f;       // static-like
        else if (mode == 3)                      coef = alpha[inst]; // blink
        else                                     coef = 0.0f;        // mode 1
        coef *= inst_valid[inst];

        const bool active = (coef != 0.0f);
        const unsigned mask = __ballot_sync(0x0000FFFFu, active);
        const unsigned lower = (1u << lane) - 1u;

        if (active) {
            const int pos = __popc(mask & lower);
            const float t0 = tp[inst * 6 + 0];
            const float t1 = tp[inst * 6 + 1];
            const float t2 = tp[inst * 6 + 2];
            const float t3 = tp[inst * 6 + 3];
            const float t4 = tp[inst * 6 + 4];
            const float t5 = tp[inst * 6 + 5];
            const float ys = (2.0f * (float)y + 1.0f) * (1.0f / (float)HH) - 1.0f;
            // ix = t0*x + bx ; iy = t3*x + by   (full chain folded)
            const float bx = 128.0f * (t1 * ys + t2) + 127.5f + 0.5f * t0 - 128.0f * t0;
            const float by = 128.0f * (t4 * ys + t5) + 127.5f + 0.5f * t3 - 128.0f * t3;
            s_act_ni[pos]   = lane;
            s_act_coef[pos] = coef;
            s_act_t0[pos]   = t0;
            s_act_t3[pos]   = t3;
            s_act_bx[pos]   = bx;
            s_act_by[pos]   = by;
        } else {
            const int pos = __popc((~mask) & 0xFFFFu & lower);
            s_inact_ni[pos] = lane;
        }
        if (lane == 0) {
            s_nact   = __popc(mask);
            s_ninact = NI - __popc(mask);
        }
    }
    __syncthreads();

    const int pix = y * WW + x;
    const float xf = (float)x;

    const int n_gpi = B * NI * CC * HW;
    const int n_mpi = B * NI * HW;
    float* __restrict__ out_gpi  = out;
    float* __restrict__ out_mpi  = out + n_gpi;
    float* __restrict__ out_gmid = out + n_gpi + n_mpi;
    float* __restrict__ out_mmid = out_gmid + B * CC * HW;
    float* __restrict__ out_ibas = out_mmid + B * HW;

    // --- zero stores for inactive instances (streaming) ---
    const int ninact = s_ninact;
    for (int k = 0; k < ninact; ++k) {
        const int ni = s_inact_ni[k];
        const int bgi = (b * NI + ni) * CC * HW + pix;
        const int bmi = (b * NI + ni) * HW + pix;
        stcs(out_gpi + bgi,          0.0f);
        stcs(out_gpi + bgi + HW,     0.0f);
        stcs(out_gpi + bgi + 2 * HW, 0.0f);
        stcs(out_mpi + bmi,          0.0f);
    }

    float gacc0 = 0.0f, gacc1 = 0.0f, gacc2 = 0.0f, macc = 0.0f;

    // --- hot loop: active instances only ---
    const int nact = s_nact;
    for (int j = 0; j < nact; ++j) {
        const int   ni   = s_act_ni[j];
        const float coef = s_act_coef[j];
        const int base_g = (b * NI + ni) * CC * HW;
        const int base_m = (b * NI + ni) * HW;

        const float ix = fmaf(s_act_t0[j], xf, s_act_bx[j]);
        const float iy = fmaf(s_act_t3[j], xf, s_act_by[j]);

        const int x0 = __float2int_rd(ix);
        const int y0 = __float2int_rd(iy);
        const float wx1 = ix - (float)x0;
        const float wy1 = iy - (float)y0;
        const float wx0 = 1.0f - wx1;
        const float wy0 = 1.0f - wy1;
        const int x1 = x0 + 1, y1 = y0 + 1;

        const bool vx0 = (x0 >= 0) & (x0 < WW);
        const bool vx1 = (x1 >= 0) & (x1 < WW);
        const bool vy0 = (y0 >= 0) & (y0 < HH);
        const bool vy1 = (y1 >= 0) & (y1 < HH);

        const int x0c = min(max(x0, 0), WW - 1);
        const int x1c = min(max(x1, 0), WW - 1);
        const int y0c = min(max(y0, 0), HH - 1);
        const int y1c = min(max(y1, 0), HH - 1);

        const float wy0c = wy0 * coef;
        const float wy1c = wy1 * coef;
        const float w00 = wx0 * wy0c * ((vx0 & vy0) ? 1.0f : 0.0f);
        const float w10 = wx1 * wy0c * ((vx1 & vy0) ? 1.0f : 0.0f);
        const float w01 = wx0 * wy1c * ((vx0 & vy1) ? 1.0f : 0.0f);
        const float w11 = wx1 * wy1c * ((vx1 & vy1) ? 1.0f : 0.0f);

        const int i00 = y0c * WW + x0c;
        const int i10 = y0c * WW + x1c;
        const int i01 = y1c * WW + x0c;
        const int i11 = y1c * WW + x1c;

        const float* __restrict__ s0 = g0 + base_g;
        const float* __restrict__ s1 = s0 + HW;
        const float* __restrict__ s2 = s1 + HW;
        const float* __restrict__ sm = m0 + base_m;

        // 16 independent loads in flight
        const float a00 = __ldg(s0 + i00), a10 = __ldg(s0 + i10),
                    a01 = __ldg(s0 + i01), a11 = __ldg(s0 + i11);
        const float b00 = __ldg(s1 + i00), b10 = __ldg(s1 + i10),
                    b01 = __ldg(s1 + i01), b11 = __ldg(s1 + i11);
        const float c00 = __ldg(s2 + i00), c10 = __ldg(s2 + i10),
                    c01 = __ldg(s2 + i01), c11 = __ldg(s2 + i11);
        const float d00 = __ldg(sm + i00), d10 = __ldg(sm + i10),
                    d01 = __ldg(sm + i01), d11 = __ldg(sm + i11);

        const float g0v = w00 * a00 + w10 * a10 + w01 * a01 + w11 * a11;
        const float g1v = w00 * b00 + w10 * b10 + w01 * b01 + w11 * b11;
        const float g2v = w00 * c00 + w10 * c10 + w01 * c01 + w11 * c11;
        const float mv  = w00 * d00 + w10 * d10 + w01 * d01 + w11 * d11;

        stcs(out_gpi + base_g + pix,          g0v);
        stcs(out_gpi + base_g + HW + pix,     g1v);
        stcs(out_gpi + base_g + 2 * HW + pix, g2v);
        stcs(out_mpi + base_m + pix,          mv);

        gacc0 += g0v; gacc1 += g1v; gacc2 += g2v; macc += mv;
    }

    // --- reductions + composite (streaming stores) ---
    const int bg = b * CC * HW + pix;
    stcs(out_gmid + bg,          gacc0);
    stcs(out_gmid + bg + HW,     gacc1);
    stcs(out_gmid + bg + 2 * HW, gacc2);
    stcs(out_mmid + b * HW + pix, fminf(fmaxf(macc, 0.0f), 1.0f));
    stcs(out_ibas + bg,          i_bg[bg]          + gacc0);
    stcs(out_ibas + bg + HW,     i_bg[bg + HW]     + gacc1);
    stcs(out_ibas + bg + 2 * HW, i_bg[bg + 2 * HW] + gacc2);
}

extern "C" void kernel_launch(void* const* d_in, const int* in_sizes, int n_in,
                              void* d_out, int out_size) {
    const float* g0          = (const float*)d_in[0];
    const float* m0          = (const float*)d_in[1];
    const float* mode_logits = (const float*)d_in[2];
    const float* tp          = (const float*)d_in[3];
    const float* alpha       = (const float*)d_in[4];
    const float* inst_valid  = (const float*)d_in[5];
    const float* i_bg        = (const float*)d_in[6];
    float* out = (float*)d_out;

    const int B = in_sizes[0] / (NI * CC * HW);

    dim3 grid(B * HH);
    dim3 block(WW);
    warp_renderer_kernel<<<grid, block>>>(g0, m0, mode_logits, tp, alpha,
                                          inst_valid, i_bg, out, B);
}

// round 8
// speedup vs baseline: 1.4168x; 1.0011x over previous
#include <cuda_runtime.h>

#define HH 256
#define WW 256
#define NI 16
#define CC 3
#define HW (HH * WW)

__device__ __forceinline__ void stcs(float* p, float v) {
#if __CUDA_ARCH__ >= 800
    __stcs(p, v);
#else
    *p = v;
#endif
}

// grid: blockIdx.x = b*256 + row2*2 + xtile  (row2 in [0,128), xtile in [0,2))
// block: 256 threads = 2 rows x 128 cols
__global__ __launch_bounds__(256, 7)
void warp_renderer_kernel(
    const float* __restrict__ g0,           // [B,NI,C,H,W]
    const float* __restrict__ m0,           // [B,NI,1,H,W]
    const float* __restrict__ mode_logits,  // [B,NI,5]
    const float* __restrict__ tp,           // [B,NI,6]
    const float* __restrict__ alpha,        // [B,NI,1]
    const float* __restrict__ inst_valid,   // [B,NI]
    const float* __restrict__ i_bg,         // [B,C,H,W]
    float* __restrict__ out,
    int B)
{
    __shared__ int   s_nact, s_ninact;
    __shared__ int   s_act_ni[NI];
    __shared__ float s_act_coef[NI];
    __shared__ float s_act_t0[NI], s_act_t3[NI];
    __shared__ float s_bx[2][NI], s_by[2][NI];
    __shared__ int   s_inact_ni[NI];

    const int b     = blockIdx.x >> 8;
    const int r     = blockIdx.x & 255;
    const int row2  = r >> 1;          // tile row pair index
    const int xtile = r & 1;           // which 128-col half
    const int ybase = row2 * 2;

    // --- per-instance precompute, both rows (warp 0: lanes 0-15 row0, 16-31 row1) ---
    if (threadIdx.x < 32) {
        const int lane = threadIdx.x & 15;
        const int row  = threadIdx.x >> 4;     // 0 or 1
        const int inst = b * NI + lane;

        const float* L = mode_logits + inst * 5;
        int mode = 0;
        float best = L[0];
        #pragma unroll
        for (int k = 1; k < 5; ++k) {
            float v = L[k];
            if (v > best) { best = v; mode = k; }  // first-max argmax
        }
        float coef;
        if (mode == 0 || mode == 2 || mode == 4) coef = 1.0f;       // static-like
        else if (mode == 3)                      coef = alpha[inst]; // blink
        else                                     coef = 0.0f;        // mode 1
        coef *= inst_valid[inst];

        const bool active = (coef != 0.0f);
        const unsigned m = __ballot_sync(0xFFFFFFFFu, active);
        const unsigned half_mask = (row == 0) ? (m & 0xFFFFu) : (m >> 16);
        const unsigned lower = (1u << lane) - 1u;

        const float t0 = tp[inst * 6 + 0];
        const float t1 = tp[inst * 6 + 1];
        const float t2 = tp[inst * 6 + 2];
        const float t3 = tp[inst * 6 + 3];
        const float t4 = tp[inst * 6 + 4];
        const float t5 = tp[inst * 6 + 5];

        if (active) {
            const int pos = __popc(half_mask & lower);
            const int yy  = ybase + row;
            const float ys = (2.0f * (float)yy + 1.0f) * (1.0f / (float)HH) - 1.0f;
            // ix = t0*x + bx ; iy = t3*x + by   (full chain folded per row)
            const float bx = 128.0f * (t1 * ys + t2) + 127.5f + 0.5f * t0 - 128.0f * t0;
            const float by = 128.0f * (t4 * ys + t5) + 127.5f + 0.5f * t3 - 128.0f * t3;
            s_bx[row][pos] = bx;
            s_by[row][pos] = by;
            if (row == 0) {
                s_act_ni[pos]   = lane;
                s_act_coef[pos] = coef;
                s_act_t0[pos]   = t0;
                s_act_t3[pos]   = t3;
            }
        } else if (row == 0) {
            const int pos = __popc((~half_mask) & 0xFFFFu & lower);
            s_inact_ni[pos] = lane;
        }
        if (threadIdx.x == 0) {
            s_nact   = __popc(half_mask);
            s_ninact = NI - __popc(half_mask);
        }
    }
    __syncthreads();

    const int xloc = threadIdx.x & 127;
    const int row  = threadIdx.x >> 7;         // 0 or 1
    const int x    = xtile * 128 + xloc;
    const int y    = ybase + row;
    const int pix  = y * WW + x;
    const float xf = (float)x;

    const int n_gpi = B * NI * CC * HW;
    const int n_mpi = B * NI * HW;
    float* __restrict__ out_gpi  = out;
    float* __restrict__ out_mpi  = out + n_gpi;
    float* __restrict__ out_gmid = out + n_gpi + n_mpi;
    float* __restrict__ out_mmid = out_gmid + B * CC * HW;
    float* __restrict__ out_ibas = out_mmid + B * HW;

    // --- zero stores for inactive instances (streaming) ---
    const int ninact = s_ninact;
    for (int k = 0; k < ninact; ++k) {
        const int ni = s_inact_ni[k];
        const int bgi = (b * NI + ni) * CC * HW + pix;
        const int bmi = (b * NI + ni) * HW + pix;
        stcs(out_gpi + bgi,          0.0f);
        stcs(out_gpi + bgi + HW,     0.0f);
        stcs(out_gpi + bgi + 2 * HW, 0.0f);
        stcs(out_mpi + bmi,          0.0f);
    }

    float gacc0 = 0.0f, gacc1 = 0.0f, gacc2 = 0.0f, macc = 0.0f;

    // --- hot loop: active instances only ---
    const int nact = s_nact;
    for (int j = 0; j < nact; ++j) {
        const int   ni   = s_act_ni[j];
        const float coef = s_act_coef[j];
        const int base_g = (b * NI + ni) * CC * HW;
        const int base_m = (b * NI + ni) * HW;

        const float ix = fmaf(s_act_t0[j], xf, s_bx[row][j]);
        const float iy = fmaf(s_act_t3[j], xf, s_by[row][j]);

        const int x0 = __float2int_rd(ix);
        const int y0 = __float2int_rd(iy);
        const float wx1 = ix - (float)x0;
        const float wy1 = iy - (float)y0;
        const float wx0 = 1.0f - wx1;
        const float wy0 = 1.0f - wy1;
        const int x1 = x0 + 1, y1 = y0 + 1;

        const bool vx0 = (x0 >= 0) & (x0 < WW);
        const bool vx1 = (x1 >= 0) & (x1 < WW);
        const bool vy0 = (y0 >= 0) & (y0 < HH);
        const bool vy1 = (y1 >= 0) & (y1 < HH);

        const int x0c = min(max(x0, 0), WW - 1);
        const int x1c = min(max(x1, 0), WW - 1);
        const int y0c = min(max(y0, 0), HH - 1);
        const int y1c = min(max(y1, 0), HH - 1);

        const float wy0c = wy0 * coef;
        const float wy1c = wy1 * coef;
        const float w00 = wx0 * wy0c * ((vx0 & vy0) ? 1.0f : 0.0f);
        const float w10 = wx1 * wy0c * ((vx1 & vy0) ? 1.0f : 0.0f);
        const float w01 = wx0 * wy1c * ((vx0 & vy1) ? 1.0f : 0.0f);
        const float w11 = wx1 * wy1c * ((vx1 & vy1) ? 1.0f : 0.0f);

        const int i00 = y0c * WW + x0c;
        const int i10 = y0c * WW + x1c;
        const int i01 = y1c * WW + x0c;
        const int i11 = y1c * WW + x1c;

        const float* __restrict__ s0 = g0 + base_g;
        const float* __restrict__ s1 = s0 + HW;
        const float* __restrict__ s2 = s1 + HW;
        const float* __restrict__ sm = m0 + base_m;

        // 16 independent loads in flight
        const float a00 = __ldg(s0 + i00), a10 = __ldg(s0 + i10),
                    a01 = __ldg(s0 + i01), a11 = __ldg(s0 + i11);
        const float b00 = __ldg(s1 + i00), b10 = __ldg(s1 + i10),
                    b01 = __ldg(s1 + i01), b11 = __ldg(s1 + i11);
        const float c00 = __ldg(s2 + i00), c10 = __ldg(s2 + i10),
                    c01 = __ldg(s2 + i01), c11 = __ldg(s2 + i11);
        const float d00 = __ldg(sm + i00), d10 = __ldg(sm + i10),
                    d01 = __ldg(sm + i01), d11 = __ldg(sm + i11);

        const float g0v = w00 * a00 + w10 * a10 + w01 * a01 + w11 * a11;
        const float g1v = w00 * b00 + w10 * b10 + w01 * b01 + w11 * b11;
        const float g2v = w00 * c00 + w10 * c10 + w01 * c01 + w11 * c11;
        const float mv  = w00 * d00 + w10 * d10 + w01 * d01 + w11 * d11;

        stcs(out_gpi + base_g + pix,          g0v);
        stcs(out_gpi + base_g + HW + pix,     g1v);
        stcs(out_gpi + base_g + 2 * HW + pix, g2v);
        stcs(out_mpi + base_m + pix,          mv);

        gacc0 += g0v; gacc1 += g1v; gacc2 += g2v; macc += mv;
    }

    // --- reductions + composite (streaming stores) ---
    const int bg = b * CC * HW + pix;
    stcs(out_gmid + bg,          gacc0);
    stcs(out_gmid + bg + HW,     gacc1);
    stcs(out_gmid + bg + 2 * HW, gacc2);
    stcs(out_mmid + b * HW + pix, fminf(fmaxf(macc, 0.0f), 1.0f));
    stcs(out_ibas + bg,          __ldg(i_bg + bg)          + gacc0);
    stcs(out_ibas + bg + HW,     __ldg(i_bg + bg + HW)     + gacc1);
    stcs(out_ibas + bg + 2 * HW, __ldg(i_bg + bg + 2 * HW) + gacc2);
}

extern "C" void kernel_launch(void* const* d_in, const int* in_sizes, int n_in,
                              void* d_out, int out_size) {
    const float* g0          = (const float*)d_in[0];
    const float* m0          = (const float*)d_in[1];
    const float* mode_logits = (const float*)d_in[2];
    const float* tp          = (const float*)d_in[3];
    const float* alpha       = (const float*)d_in[4];
    const float* inst_valid  = (const float*)d_in[5];
    const float* i_bg        = (const float*)d_in[6];
    float* out = (float*)d_out;

    const int B = in_sizes[0] / (NI * CC * HW);

    dim3 grid(B * HH);   // b*256 + row2*2 + xtile
    dim3 block(256);
    warp_renderer_kernel<<<grid, block>>>(g0, m0, mode_logits, tp, alpha,
                                          inst_valid, i_bg, out, B);
}